// round 2
// baseline (speedup 1.0000x reference)
#include <cuda_runtime.h>

#define BATCH 4
#define CIN   64
#define HH    128
#define WW    128
#define COUT  128
#define HW    (HH*WW)        // 16384
#define NPX   (BATCH*HW)     // 65536

// ---------------- scratch (device globals; no allocation allowed) ----------------
__device__ float  g_xt[BATCH*HW*CIN];     // x transposed to NHWC: [b][h][w][c]
__device__ float  g_wT[9*CIN*COUT];       // weight transposed: [k][c][o]
__device__ int    g_ppi[9*NPX];           // packed clamped corner coords per (k, pixel)
__device__ float4 g_ppw[9*NPX];           // bilinear weights (mask+validity folded) per (k, pixel)

// ---------------- kernel: transpose x (NCHW -> NHWC) ----------------
__global__ __launch_bounds__(256) void k_transpose_x(const float* __restrict__ x) {
    __shared__ float tile[64*129];
    int bid = blockIdx.x;              // b*128 + h
    int b = bid >> 7, h = bid & 127;
    int t = threadIdx.x;
    const float* xp = x + ((size_t)b*64*HW) + (size_t)h*WW;
    for (int i = t; i < 64*128; i += 256) {
        int c = i >> 7, w = i & 127;
        tile[c*129 + w] = xp[(size_t)c*HW + w];
    }
    __syncthreads();
    float4* out4 = (float4*)g_xt;
    for (int i = t; i < 2048; i += 256) {
        int w = i >> 4, cq = i & 15;
        float4 v;
        v.x = tile[(cq*4+0)*129 + w];
        v.y = tile[(cq*4+1)*129 + w];
        v.z = tile[(cq*4+2)*129 + w];
        v.w = tile[(cq*4+3)*129 + w];
        out4[(size_t)(bid*128 + w)*16 + cq] = v;
    }
}

// ---------------- kernel: transpose weight (O,C,9) -> (9,C,O) ----------------
__global__ __launch_bounds__(256) void k_transpose_w(const float* __restrict__ weight) {
    int idx = blockIdx.x*256 + threadIdx.x;
    if (idx < 9*64*128) {
        int k = idx / 8192;
        int r = idx & 8191;
        int c = r >> 7, o = r & 127;
        g_wT[idx] = weight[(o*64 + c)*9 + k];
    }
}

// ---------------- kernel: offset/mask conv + sampling-parameter precompute ----------------
// grid (4, 16, 4): 32x8 pixel tile per block, 128 threads, 2 rows per thread.
__global__ __launch_bounds__(128) void k_offset(
    const float* __restrict__ x,
    const float* __restrict__ w_off, const float* __restrict__ b_off,
    const float* __restrict__ w_mask, const float* __restrict__ b_mask)
{
    __shared__ float xs[8*10*34];    // [c][row][col], chunk of 8 channels, 10x34 halo tile
    __shared__ float wsh[27*8*9];    // [co][c][p]
    int t   = threadIdx.x;
    int tx  = t & 31, tyg = t >> 5;  // tyg in 0..3; thread owns rows tyg and tyg+4
    int w0  = blockIdx.x * 32;
    int h0  = blockIdx.y * 8;
    int b   = blockIdx.z;

    float acc0[27], acc1[27];
    #pragma unroll
    for (int i = 0; i < 27; ++i) { acc0[i] = 0.f; acc1[i] = 0.f; }

    for (int cc = 0; cc < 8; ++cc) {
        for (int i = t; i < 8*10*34; i += 128) {
            int c = i / 340;
            int rem = i - c*340;
            int r = rem / 34, col = rem - r*34;
            int gy = h0 - 1 + r, gx = w0 - 1 + col;
            float v = 0.f;
            if ((unsigned)gy < 128u && (unsigned)gx < 128u)
                v = x[(size_t)((b*64 + cc*8 + c)*128 + gy)*128 + gx];
            xs[i] = v;
        }
        for (int i = t; i < 27*8*9; i += 128) {
            int co = i / 72;
            int rem = i - co*72;
            int c = rem / 9, p = rem - c*9;
            float v;
            if (co < 18) v = w_off[(co*64 + cc*8 + c)*9 + p];
            else         v = w_mask[((co-18)*64 + cc*8 + c)*9 + p];
            wsh[i] = v;
        }
        __syncthreads();
        for (int c = 0; c < 8; ++c) {
            #pragma unroll
            for (int p = 0; p < 9; ++p) {
                const int ky = p/3, kx = p%3;
                float xv0 = xs[c*340 + (tyg+ky)*34   + tx + kx];
                float xv1 = xs[c*340 + (tyg+4+ky)*34 + tx + kx];
                #pragma unroll
                for (int co = 0; co < 27; ++co) {
                    float wv = wsh[co*72 + c*9 + p];
                    acc0[co] += xv0 * wv;
                    acc1[co] += xv1 * wv;
                }
            }
        }
        __syncthreads();
    }

    // epilogue: turn (offset, mask) into packed corner coords + bilinear weights
    auto epi = [&](float (&A)[27], int hrow) {
        int wglob = w0 + tx;
        int pxg = ((b << 7) + hrow)*128 + wglob;
        #pragma unroll
        for (int kk = 0; kk < 9; ++kk) {
            float dy = A[2*kk]   + b_off[2*kk];
            float dx = A[2*kk+1] + b_off[2*kk+1];
            float mz = A[18+kk]  + b_mask[kk];
            float m  = 1.0f / (1.0f + __expf(-mz));
            float py  = (float)(hrow  - 1 + kk/3) + dy;
            float pxx = (float)(wglob - 1 + kk%3) + dx;
            float y0f = floorf(py), x0f = floorf(pxx);
            float ly = py - y0f, lx = pxx - x0f;
            int y0 = (int)y0f, x0i = (int)x0f;
            int y1 = y0 + 1,  x1i = x0i + 1;
            float w00 = (1.f-ly)*(1.f-lx)*m;
            float w01 = (1.f-ly)*lx*m;
            float w10 = ly*(1.f-lx)*m;
            float w11 = ly*lx*m;
            if (y0  < 0 || y0  > 127) { w00 = 0.f; w01 = 0.f; }
            if (y1  < 0 || y1  > 127) { w10 = 0.f; w11 = 0.f; }
            if (x0i < 0 || x0i > 127) { w00 = 0.f; w10 = 0.f; }
            if (x1i < 0 || x1i > 127) { w01 = 0.f; w11 = 0.f; }
            int y0c = min(max(y0, 0), 127),  y1c = min(max(y1, 0), 127);
            int x0c = min(max(x0i, 0), 127), x1c = min(max(x1i, 0), 127);
            g_ppi[kk*NPX + pxg] = y0c | (y1c << 8) | (x0c << 16) | (x1c << 24);
            g_ppw[kk*NPX + pxg] = make_float4(w00, w01, w10, w11);
        }
    };
    epi(acc0, h0 + tyg);
    epi(acc1, h0 + tyg + 4);
}

// ---------------- kernel: deformable sampling + implicit GEMM ----------------
// grid 512 (b*128+h), 256 threads. Per block: 128 pixels (one output row) x 128 outputs.
// dynamic smem: ws[64][128] (32KB) + samp[128][68] (34.8KB) = 67584 B (reused for epilogue)
__global__ __launch_bounds__(256, 2) void k_deform(float* __restrict__ out) {
    extern __shared__ float sm[];
    float* wsm  = sm;          // 8192 floats: ws[c][o]
    float* samp = sm + 8192;   // 128*68 floats: samp[px][c], pitch 68

    int t   = threadIdx.x;
    int bid = blockIdx.x;               // b*128 + h
    int b   = bid >> 7, h = bid & 127;
    const float* xb = g_xt + ((size_t)b << 20);  // b * HW * 64

    float4 acc[16];
    #pragma unroll
    for (int i = 0; i < 16; ++i) acc[i] = make_float4(0.f, 0.f, 0.f, 0.f);

    int og = t & 31, pg = t >> 5;
    int o0 = og << 2;        // 4 consecutive outputs
    int p0 = pg << 4;        // 16 consecutive pixels

    for (int k = 0; k < 9; ++k) {
        __syncthreads();
        // stage weights for this kernel position: wT[k][c][o], contiguous copy
        {
            const float4* wk = (const float4*)(g_wT + k*8192);
            float4* w4 = (float4*)wsm;
            #pragma unroll
            for (int j = 0; j < 8; ++j) w4[t + j*256] = wk[t + j*256];
        }
        // sampling: 128 px * 16 float4-chunks = 2048 tasks, 8 per thread
        {
            int ppb = k*NPX + bid*128;
            #pragma unroll
            for (int j = 0; j < 8; ++j) {
                int task = t + j*256;
                int cq = task & 15, px = task >> 4;
                int    pc = g_ppi[ppb + px];
                float4 wg = g_ppw[ppb + px];
                int y0 =  pc        & 255;
                int y1 = (pc >>  8) & 255;
                int x0 = (pc >> 16) & 255;
                int x1 = (pc >> 24) & 255;
                const float4* r00 = (const float4*)(xb + (size_t)(((y0<<7)+x0)<<6)) + cq;
                const float4* r01 = (const float4*)(xb + (size_t)(((y0<<7)+x1)<<6)) + cq;
                const float4* r10 = (const float4*)(xb + (size_t)(((y1<<7)+x0)<<6)) + cq;
                const float4* r11 = (const float4*)(xb + (size_t)(((y1<<7)+x1)<<6)) + cq;
                float4 a = *r00, bb = *r01, cc = *r10, dd = *r11;
                float4 v;
                v.x = wg.x*a.x + wg.y*bb.x + wg.z*cc.x + wg.w*dd.x;
                v.y = wg.x*a.y + wg.y*bb.y + wg.z*cc.y + wg.w*dd.y;
                v.z = wg.x*a.z + wg.y*bb.z + wg.z*cc.z + wg.w*dd.z;
                v.w = wg.x*a.w + wg.y*bb.w + wg.z*cc.w + wg.w*dd.w;
                *(float4*)(samp + px*68 + (cq << 2)) = v;
            }
        }
        __syncthreads();
        // GEMM accumulate: acc[p][o] over this k's 64 channels
        #pragma unroll 4
        for (int c = 0; c < 64; ++c) {
            float4 w4 = *(const float4*)(wsm + (c << 7) + o0);
            #pragma unroll
            for (int i = 0; i < 16; ++i) {
                float s = samp[(p0 + i)*68 + c];
                acc[i].x += s * w4.x;
                acc[i].y += s * w4.y;
                acc[i].z += s * w4.z;
                acc[i].w += s * w4.w;
            }
        }
    }
    __syncthreads();
    // epilogue: transpose 128px x 128o tile through smem, then coalesced NCHW stores
    float* smo = sm;   // pitch 132, needs 127*132+127+1 = 16892 <= 16896 floats
    #pragma unroll
    for (int i = 0; i < 16; ++i)
        *(float4*)(smo + (p0 + i)*132 + o0) = acc[i];
    __syncthreads();
    float* op = out + ((size_t)b*128)*16384 + (size_t)h*128;
    for (int idx = t; idx < 16384; idx += 256) {
        int o = idx >> 7, px = idx & 127;
        op[(size_t)o*16384 + px] = smo[px*132 + o];
    }
}

// ---------------- launch ----------------
extern "C" void kernel_launch(void* const* d_in, const int* in_sizes, int n_in,
                              void* d_out, int out_size) {
    const float* x      = (const float*)d_in[0];
    const float* w_off  = (const float*)d_in[1];
    const float* b_off  = (const float*)d_in[2];
    const float* w_mask = (const float*)d_in[3];
    const float* b_mask = (const float*)d_in[4];
    const float* weight = (const float*)d_in[5];
    float* out = (float*)d_out;

    (void)cudaFuncSetAttribute(k_deform, cudaFuncAttributeMaxDynamicSharedMemorySize, 67584);

    k_transpose_x<<<512, 256>>>(x);
    k_transpose_w<<<288, 256>>>(weight);
    k_offset<<<dim3(4, 16, 4), 128>>>(x, w_off, b_off, w_mask, b_mask);
    k_deform<<<512, 256, 67584>>>(out);
}

// round 5
// speedup vs baseline: 1.6587x; 1.6587x over previous
#include <cuda_runtime.h>
#include <cuda_bf16.h>
#include <cstdint>

#define BATCH 4
#define CIN   64
#define HH    128
#define WW    128
#define COUT  128
#define HW    (HH*WW)        // 16384
#define NPX   (BATCH*HW)     // 65536

// ---------------- scratch (device globals; no allocation allowed) ----------------
__device__ float  g_xt[BATCH*HW*CIN];     // x transposed to NHWC: [b][h][w][c]
__device__ int    g_ppi[9*NPX];           // packed clamped corner coords per (k, pixel)
__device__ float4 g_ppw[9*NPX];           // bilinear weights (mask+validity folded)
// weights split hi/lo, padded pitch-72 layout: [k][o][72] bf16
__device__ __align__(16) __nv_bfloat16 g_wbh[9*128*72];
__device__ __align__(16) __nv_bfloat16 g_wbl[9*128*72];

// ---------------- helpers ----------------
__device__ __forceinline__ uint32_t smem_u32(const void* p) {
    uint32_t a;
    asm("{ .reg .u64 t; cvta.to.shared.u64 t, %1; cvt.u32.u64 %0, t; }" : "=r"(a) : "l"(p));
    return a;
}
__device__ __forceinline__ void ldsm_x4(uint32_t (&r)[4], uint32_t addr) {
    asm volatile("ldmatrix.sync.aligned.m8n8.x4.shared.b16 {%0, %1, %2, %3}, [%4];"
                 : "=r"(r[0]), "=r"(r[1]), "=r"(r[2]), "=r"(r[3]) : "r"(addr));
}
__device__ __forceinline__ void mma16816(float (&d)[4], const uint32_t (&a)[4],
                                         uint32_t b0, uint32_t b1) {
    asm volatile(
        "mma.sync.aligned.m16n8k16.row.col.f32.bf16.bf16.f32 "
        "{%0, %1, %2, %3}, {%4, %5, %6, %7}, {%8, %9}, {%0, %1, %2, %3};"
        : "+f"(d[0]), "+f"(d[1]), "+f"(d[2]), "+f"(d[3])
        : "r"(a[0]), "r"(a[1]), "r"(a[2]), "r"(a[3]), "r"(b0), "r"(b1));
}

// ---------------- kernel: transpose x (NCHW -> NHWC) ----------------
__global__ __launch_bounds__(256) void k_transpose_x(const float* __restrict__ x) {
    __shared__ float tile[64*129];
    int bid = blockIdx.x;              // b*128 + h
    int b = bid >> 7, h = bid & 127;
    int t = threadIdx.x;
    const float* xp = x + ((size_t)b*64*HW) + (size_t)h*WW;
    for (int i = t; i < 64*128; i += 256) {
        int c = i >> 7, w = i & 127;
        tile[c*129 + w] = xp[(size_t)c*HW + w];
    }
    __syncthreads();
    float4* out4 = (float4*)g_xt;
    for (int i = t; i < 2048; i += 256) {
        int w = i >> 4, cq = i & 15;
        float4 v;
        v.x = tile[(cq*4+0)*129 + w];
        v.y = tile[(cq*4+1)*129 + w];
        v.z = tile[(cq*4+2)*129 + w];
        v.w = tile[(cq*4+3)*129 + w];
        out4[(size_t)(bid*128 + w)*16 + cq] = v;
    }
}

// ---------------- kernel: weight split hi/lo, (O,C,9) -> [k][o][72] ----------------
__global__ __launch_bounds__(256) void k_wsplit(const float* __restrict__ weight) {
    int idx = blockIdx.x*256 + threadIdx.x;
    if (idx < 9*128*72) {
        int k = idx / 9216;
        int r = idx - k*9216;
        int o = r / 72, c = r - o*72;
        float v = (c < 64) ? weight[(o*64 + c)*9 + k] : 0.f;
        __nv_bfloat16 hi = __float2bfloat16_rn(v);
        __nv_bfloat16 lo = __float2bfloat16_rn(v - __bfloat162float(hi));
        g_wbh[idx] = hi;
        g_wbl[idx] = lo;
    }
}

// ---------------- kernel: offset/mask conv + sampling-parameter precompute ----------------
__global__ __launch_bounds__(128) void k_offset(
    const float* __restrict__ x,
    const float* __restrict__ w_off, const float* __restrict__ b_off,
    const float* __restrict__ w_mask, const float* __restrict__ b_mask)
{
    __shared__ float xs[8*10*34];
    __shared__ float wsh[27*8*9];
    int t   = threadIdx.x;
    int tx  = t & 31, tyg = t >> 5;
    int w0  = blockIdx.x * 32;
    int h0  = blockIdx.y * 8;
    int b   = blockIdx.z;

    float acc0[27], acc1[27];
    #pragma unroll
    for (int i = 0; i < 27; ++i) { acc0[i] = 0.f; acc1[i] = 0.f; }

    for (int cc = 0; cc < 8; ++cc) {
        for (int i = t; i < 8*10*34; i += 128) {
            int c = i / 340;
            int rem = i - c*340;
            int r = rem / 34, col = rem - r*34;
            int gy = h0 - 1 + r, gx = w0 - 1 + col;
            float v = 0.f;
            if ((unsigned)gy < 128u && (unsigned)gx < 128u)
                v = x[(size_t)((b*64 + cc*8 + c)*128 + gy)*128 + gx];
            xs[i] = v;
        }
        for (int i = t; i < 27*8*9; i += 128) {
            int co = i / 72;
            int rem = i - co*72;
            int c = rem / 9, p = rem - c*9;
            float v;
            if (co < 18) v = w_off[(co*64 + cc*8 + c)*9 + p];
            else         v = w_mask[((co-18)*64 + cc*8 + c)*9 + p];
            wsh[i] = v;
        }
        __syncthreads();
        for (int c = 0; c < 8; ++c) {
            #pragma unroll
            for (int p = 0; p < 9; ++p) {
                const int ky = p/3, kx = p%3;
                float xv0 = xs[c*340 + (tyg+ky)*34   + tx + kx];
                float xv1 = xs[c*340 + (tyg+4+ky)*34 + tx + kx];
                #pragma unroll
                for (int co = 0; co < 27; ++co) {
                    float wv = wsh[co*72 + c*9 + p];
                    acc0[co] += xv0 * wv;
                    acc1[co] += xv1 * wv;
                }
            }
        }
        __syncthreads();
    }

    auto epi = [&](float (&A)[27], int hrow) {
        int wglob = w0 + tx;
        int pxg = ((b << 7) + hrow)*128 + wglob;
        #pragma unroll
        for (int kk = 0; kk < 9; ++kk) {
            float dy = A[2*kk]   + b_off[2*kk];
            float dx = A[2*kk+1] + b_off[2*kk+1];
            float mz = A[18+kk]  + b_mask[kk];
            float m  = 1.0f / (1.0f + __expf(-mz));
            float py  = (float)(hrow  - 1 + kk/3) + dy;
            float pxx = (float)(wglob - 1 + kk%3) + dx;
            float y0f = floorf(py), x0f = floorf(pxx);
            float ly = py - y0f, lx = pxx - x0f;
            int y0 = (int)y0f, x0i = (int)x0f;
            int y1 = y0 + 1,  x1i = x0i + 1;
            float w00 = (1.f-ly)*(1.f-lx)*m;
            float w01 = (1.f-ly)*lx*m;
            float w10 = ly*(1.f-lx)*m;
            float w11 = ly*lx*m;
            if (y0  < 0 || y0  > 127) { w00 = 0.f; w01 = 0.f; }
            if (y1  < 0 || y1  > 127) { w10 = 0.f; w11 = 0.f; }
            if (x0i < 0 || x0i > 127) { w00 = 0.f; w10 = 0.f; }
            if (x1i < 0 || x1i > 127) { w01 = 0.f; w11 = 0.f; }
            int y0c = min(max(y0, 0), 127),  y1c = min(max(y1, 0), 127);
            int x0c = min(max(x0i, 0), 127), x1c = min(max(x1i, 0), 127);
            g_ppi[kk*NPX + pxg] = y0c | (y1c << 8) | (x0c << 16) | (x1c << 24);
            g_ppw[kk*NPX + pxg] = make_float4(w00, w01, w10, w11);
        }
    };
    epi(acc0, h0 + tyg);
    epi(acc1, h0 + tyg + 4);
}

// ---------------- kernel: deformable sampling + bf16 split mma.sync GEMM ----------------
// grid 512 (b*128+h), 256 threads (8 warps, 4x2: warp_m in 0..3 -> 32 px, warp_n in 0..1 -> 64 out).
// smem (pitch 144B rows, conflict-free for ldmatrix):
//   A_HI@0 (18432 B), A_LO@18432, B_HI@36864, B_LO@55296; total 73728 B.
#define SA_HI 0
#define SA_LO 18432
#define SB_HI 36864
#define SB_LO 55296
#define SMEM_TOT 73728

__global__ __launch_bounds__(256) void k_deform_mma(float* __restrict__ out) {
    extern __shared__ char sm[];
    uint32_t sb = smem_u32(sm);
    int t    = threadIdx.x;
    int wid  = t >> 5, lane = t & 31;
    int bid  = blockIdx.x;
    int b    = bid >> 7, h = bid & 127;
    const float* xb = g_xt + ((size_t)b << 20);

    int warp_m = wid & 3;        // 0..3: px group of 32
    int warp_n = wid >> 2;       // 0..1: out group of 64
    int m0base = warp_m * 32;
    int n0base = warp_n * 64;

    float acc[2][8][4];          // [mtile][ntile8][frag]
    #pragma unroll
    for (int i = 0; i < 2; ++i)
        #pragma unroll
        for (int j = 0; j < 8; ++j)
            #pragma unroll
            for (int q = 0; q < 4; ++q) acc[i][j][q] = 0.f;

    // ldmatrix lane addressing: matrix0 = rows 0-7 @k+0, m1 = rows 8-15 @k+0,
    // m2 = rows 0-7 @k+8, m3 = rows 8-15 @k+8
    int lrow = (lane & 7) + ((lane >> 3) & 1) * 8;   // row within 16
    int lcol = (lane & 16) ? 8 : 0;                  // k offset within 16

    for (int k = 0; k < 9; ++k) {
        __syncthreads();   // previous tap's ldmatrix reads done before overwrite
        // ---- stage B tiles (pre-split, pre-padded in global) ----
        {
            const uint4* srcH = (const uint4*)(g_wbh + k*9216);
            const uint4* srcL = (const uint4*)(g_wbl + k*9216);
            uint4* dstH = (uint4*)(sm + SB_HI);
            uint4* dstL = (uint4*)(sm + SB_LO);
            for (int i = t; i < 1152; i += 256) { dstH[i] = srcH[i]; dstL[i] = srcL[i]; }
        }
        // ---- sampling: 128 px * 16 chunks of 4 channels ----
        {
            int ppb = k*NPX + bid*128;
            #pragma unroll
            for (int j = 0; j < 8; ++j) {
                int task = t + j*256;
                int cq = task & 15, px = task >> 4;
                int    pc = g_ppi[ppb + px];
                float4 wg = g_ppw[ppb + px];
                int y0 =  pc        & 255;
                int y1 = (pc >>  8) & 255;
                int x0 = (pc >> 16) & 255;
                int x1 = (pc >> 24) & 255;
                const float4* r00 = (const float4*)(xb + (size_t)(((y0<<7)+x0)<<6)) + cq;
                const float4* r01 = (const float4*)(xb + (size_t)(((y0<<7)+x1)<<6)) + cq;
                const float4* r10 = (const float4*)(xb + (size_t)(((y1<<7)+x0)<<6)) + cq;
                const float4* r11 = (const float4*)(xb + (size_t)(((y1<<7)+x1)<<6)) + cq;
                float4 a = *r00, bb = *r01, cc = *r10, dd = *r11;
                float4 v;
                v.x = wg.x*a.x + wg.y*bb.x + wg.z*cc.x + wg.w*dd.x;
                v.y = wg.x*a.y + wg.y*bb.y + wg.z*cc.y + wg.w*dd.y;
                v.z = wg.x*a.z + wg.y*bb.z + wg.z*cc.z + wg.w*dd.z;
                v.w = wg.x*a.w + wg.y*bb.w + wg.z*cc.w + wg.w*dd.w;
                __nv_bfloat16 hx = __float2bfloat16_rn(v.x), hy = __float2bfloat16_rn(v.y);
                __nv_bfloat16 hz = __float2bfloat16_rn(v.z), hw = __float2bfloat16_rn(v.w);
                __nv_bfloat16 lx2 = __float2bfloat16_rn(v.x - __bfloat162float(hx));
                __nv_bfloat16 ly2 = __float2bfloat16_rn(v.y - __bfloat162float(hy));
                __nv_bfloat16 lz2 = __float2bfloat16_rn(v.z - __bfloat162float(hz));
                __nv_bfloat16 lw2 = __float2bfloat16_rn(v.w - __bfloat162float(hw));
                uint32_t h01 = ((uint32_t)__bfloat16_as_ushort(hy) << 16) | __bfloat16_as_ushort(hx);
                uint32_t h23 = ((uint32_t)__bfloat16_as_ushort(hw) << 16) | __bfloat16_as_ushort(hz);
                uint32_t l01 = ((uint32_t)__bfloat16_as_ushort(ly2) << 16) | __bfloat16_as_ushort(lx2);
                uint32_t l23 = ((uint32_t)__bfloat16_as_ushort(lw2) << 16) | __bfloat16_as_ushort(lz2);
                int off = px*144 + cq*8;
                *(uint2*)(sm + SA_HI + off) = make_uint2(h01, h23);
                *(uint2*)(sm + SA_LO + off) = make_uint2(l01, l23);
            }
        }
        __syncthreads();

        // ---- MMA: 4 ksteps of 16, split passes ----
        #pragma unroll
        for (int ks = 0; ks < 4; ++ks) {
            int kc = ks*16 + lcol;
            uint32_t ah[2][4], al[2][4], bh[4][4], bl[4][4];
            #pragma unroll
            for (int mt = 0; mt < 2; ++mt) {
                uint32_t aoff = (uint32_t)((m0base + mt*16 + lrow)*144 + kc*2);
                ldsm_x4(ah[mt], sb + SA_HI + aoff);
                ldsm_x4(al[mt], sb + SA_LO + aoff);
            }
            #pragma unroll
            for (int ng = 0; ng < 4; ++ng) {
                uint32_t boff = (uint32_t)((n0base + ng*16 + lrow)*144 + kc*2);
                ldsm_x4(bh[ng], sb + SB_HI + boff);
                ldsm_x4(bl[ng], sb + SB_LO + boff);
            }
            // B fragment pairing: n-octet 0 = (r0, r2), n-octet 1 = (r1, r3)
            #pragma unroll
            for (int mt = 0; mt < 2; ++mt) {
                #pragma unroll
                for (int ng = 0; ng < 4; ++ng) {
                    mma16816(acc[mt][2*ng],   ah[mt], bh[ng][0], bh[ng][2]);
                    mma16816(acc[mt][2*ng+1], ah[mt], bh[ng][1], bh[ng][3]);
                    mma16816(acc[mt][2*ng],   al[mt], bh[ng][0], bh[ng][2]);
                    mma16816(acc[mt][2*ng+1], al[mt], bh[ng][1], bh[ng][3]);
                    mma16816(acc[mt][2*ng],   ah[mt], bl[ng][0], bl[ng][2]);
                    mma16816(acc[mt][2*ng+1], ah[mt], bl[ng][1], bl[ng][3]);
                }
            }
        }
    }

    // ---- epilogue: frags -> smem [px][o] (pitch 132), then coalesced NCHW stores ----
    __syncthreads();
    float* smo = (float*)sm;
    int qrow = lane >> 2, qcol = (lane & 3) * 2;
    #pragma unroll
    for (int mt = 0; mt < 2; ++mt) {
        #pragma unroll
        for (int nt = 0; nt < 8; ++nt) {
            int px0 = m0base + mt*16 + qrow;
            int o0  = n0base + nt*8 + qcol;
            *(float2*)(smo + px0*132 + o0)       = make_float2(acc[mt][nt][0], acc[mt][nt][1]);
            *(float2*)(smo + (px0+8)*132 + o0)   = make_float2(acc[mt][nt][2], acc[mt][nt][3]);
        }
    }
    __syncthreads();
    float* op = out + ((size_t)b*128)*16384 + (size_t)h*128;
    for (int idx = t; idx < 16384; idx += 256) {
        int o = idx >> 7, px = idx & 127;
        op[(size_t)o*16384 + px] = smo[px*132 + o];
    }
}

// ---------------- launch ----------------
extern "C" void kernel_launch(void* const* d_in, const int* in_sizes, int n_in,
                              void* d_out, int out_size) {
    const float* x      = (const float*)d_in[0];
    const float* w_off  = (const float*)d_in[1];
    const float* b_off  = (const float*)d_in[2];
    const float* w_mask = (const float*)d_in[3];
    const float* b_mask = (const float*)d_in[4];
    const float* weight = (const float*)d_in[5];
    float* out = (float*)d_out;

    (void)cudaFuncSetAttribute(k_deform_mma, cudaFuncAttributeMaxDynamicSharedMemorySize, SMEM_TOT);

    k_transpose_x<<<512, 256>>>(x);
    k_wsplit<<<(9*128*72 + 255)/256, 256>>>(weight);
    k_offset<<<dim3(4, 16, 4), 128>>>(x, w_off, b_off, w_mask, b_mask);
    k_deform_mma<<<512, 256, SMEM_TOT>>>(out);
}